// round 11
// baseline (speedup 1.0000x reference)
#include <cuda_runtime.h>

#define NS   512
#define NS2  (NS * NS)
#define TN   20000
#define ND   2000
#define DTC  30.0f
#define RAD  8          // fill radix (anchors every 8 rows)
#define NANCH 2500      // TN / RAD
#define SKROWS 1280     // split-K partial rows for anchor BK (max cnt = 1250)

// ---------------- static scratch (no allocations allowed) ----------------
__device__ float d_Lt[NS2];               // (dt*A)^T
__device__ float d_G1[NS2];               // Lt^2
__device__ float d_G2[NS2];               // H = Lt/6 + Lt^2/24
// T slots: 0 = Horner base (I+Lt+Lt^2/2) ; 1..8 = (M^q)^T ; 9=T16,10=T32,11=T64,12=T128
__device__ float d_T[13][NS2];
__device__ float d_vec[8 * NS];           // temps g,h,Lg,L2g,L3g,Lh,L2h,L3h
__device__ float d_vw[RAD * 5 * NS];      // vw[j] = M^j [w1..w4, v]
__device__ float d_cv[RAD * NS];          // cv[p-1] = sum_{j<p} M^j v
__device__ float d_part[16 * NS2];        // split-K partials (16.8 MB, reused)

// ---------------- small helpers ----------------
__global__ void k_tpose(const float* __restrict__ A, float* __restrict__ Lt) {
    int idx = blockIdx.x * blockDim.x + threadIdx.x;
    if (idx < NS2) {
        int i = idx >> 9, j = idx & 511;
        Lt[idx] = DTC * A[j * NS + i];
    }
}

__global__ void k_gh(const float* __restrict__ B, const float* __restrict__ Q,
                     float* __restrict__ g, float* __restrict__ h) {
    int i = blockIdx.x * blockDim.x + threadIdx.x;
    if (i < NS) {
        g[i] = B[i * 9];
        float s = 0.f;
#pragma unroll
        for (int m = 0; m < 8; m++) s += B[i * 9 + 1 + m] * Q[m];
        h[i] = s;
    }
}

__global__ void k_matvec2(const float* __restrict__ A,
                          const float* __restrict__ x1, const float* __restrict__ x2,
                          float* __restrict__ y1, float* __restrict__ y2, float scale) {
    __shared__ float red1[128], red2[128];
    int row = blockIdx.x;
    float s1 = 0.f, s2 = 0.f;
    for (int j = threadIdx.x; j < NS; j += 128) {
        float a = A[row * NS + j];
        s1 += a * x1[j];
        s2 += a * x2[j];
    }
    red1[threadIdx.x] = s1; red2[threadIdx.x] = s2;
    __syncthreads();
    for (int st = 64; st > 0; st >>= 1) {
        if (threadIdx.x < st) {
            red1[threadIdx.x] += red1[threadIdx.x + st];
            red2[threadIdx.x] += red2[threadIdx.x + st];
        }
        __syncthreads();
    }
    if (threadIdx.x == 0) { y1[row] = scale * red1[0]; y2[row] = scale * red2[0]; }
}

// w1..w4, v into vw[0]
__global__ void k_combine(const float* __restrict__ vec, float* __restrict__ vw) {
    int i = blockIdx.x * blockDim.x + threadIdx.x;
    if (i >= NS) return;
    const float G   = vec[0 * NS + i], H   = vec[1 * NS + i];
    const float LG  = vec[2 * NS + i], L2G = vec[3 * NS + i], L3G = vec[4 * NS + i];
    const float LH  = vec[5 * NS + i], L2H = vec[6 * NS + i], L3H = vec[7 * NS + i];
    const float c = DTC / 8.0f;
    vw[0 * NS + i] = c * (G + LG + (L2G + L3G) * (1.0f / 3.0f));
    vw[1 * NS + i] = c * (3.0f * G + 2.0f * LG + L2G);
    vw[2 * NS + i] = c * (3.0f * G + LG);
    vw[3 * NS + i] = c * G;
    vw[4 * NS + i] = DTC * (H + 0.5f * LH + L2H * (1.0f / 6.0f) + L3H * (1.0f / 24.0f));
}

// H = Lt/6 + G1/24 ; base(T0) = I + Lt + G1/2
__global__ void k_prep1(const float* __restrict__ Lt, const float* __restrict__ G1,
                        float* __restrict__ H, float* __restrict__ base) {
    int idx = blockIdx.x * blockDim.x + threadIdx.x;
    if (idx < NS2) {
        int i = idx >> 9, j = idx & 511;
        float l = Lt[idx], g = G1[idx];
        H[idx]    = l * (1.0f / 6.0f) + g * (1.0f / 24.0f);
        base[idx] = l + 0.5f * g + (i == j ? 1.0f : 0.0f);
    }
}

// ---------------- split-K 512^3 GEMM partials (32x64 tile, K chunk 128) ----------------
__global__ void __launch_bounds__(128) k_gsk(
    const float* __restrict__ A, const float* __restrict__ B, float* __restrict__ part)
{
    __shared__ float As[16][36];
    __shared__ float Bs[16][68];
    const int t  = threadIdx.x;
    const int tx = t & 7, ty = t >> 3;
    const int r0 = blockIdx.y * 32, c0 = blockIdx.x * 64;
    const int kb = blockIdx.z * 128;

    const int ar = t >> 2, ac4 = (t & 3) * 4;
    const int br = t >> 4, bc4 = (t & 15) * 4;

    unsigned long long acc[2][4];
#pragma unroll
    for (int m = 0; m < 2; m++)
#pragma unroll
        for (int p = 0; p < 4; p++) acc[m][p] = 0ull;

    float4 av = *(const float4*)(A + (size_t)(r0 + ar) * NS + kb + ac4);
    float4 b0 = *(const float4*)(B + (size_t)(kb + br) * NS + c0 + bc4);
    float4 b1 = *(const float4*)(B + (size_t)(kb + br + 8) * NS + c0 + bc4);

    for (int it = 0; it < 8; ++it) {
        As[ac4 + 0][ar] = av.x; As[ac4 + 1][ar] = av.y;
        As[ac4 + 2][ar] = av.z; As[ac4 + 3][ar] = av.w;
        *(float4*)&Bs[br][bc4]     = b0;
        *(float4*)&Bs[br + 8][bc4] = b1;
        __syncthreads();
        if (it < 7) {
            const int k0 = kb + (it + 1) * 16;
            av = *(const float4*)(A + (size_t)(r0 + ar) * NS + k0 + ac4);
            b0 = *(const float4*)(B + (size_t)(k0 + br) * NS + c0 + bc4);
            b1 = *(const float4*)(B + (size_t)(k0 + br + 8) * NS + c0 + bc4);
        }
#pragma unroll
        for (int kk = 0; kk < 16; ++kk) {
            float a0 = As[kk][ty * 2 + 0];
            float a1 = As[kk][ty * 2 + 1];
            ulonglong2 bp0 = *(const ulonglong2*)&Bs[kk][tx * 8];
            ulonglong2 bp1 = *(const ulonglong2*)&Bs[kk][tx * 8 + 4];
            unsigned long long bv[4] = {bp0.x, bp0.y, bp1.x, bp1.y};
            unsigned long long av0, av1;
            asm("mov.b64 %0, {%1, %1};" : "=l"(av0) : "f"(a0));
            asm("mov.b64 %0, {%1, %1};" : "=l"(av1) : "f"(a1));
#pragma unroll
            for (int p = 0; p < 4; p++) {
                asm("fma.rn.f32x2 %0, %1, %2, %0;" : "+l"(acc[0][p]) : "l"(av0), "l"(bv[p]));
                asm("fma.rn.f32x2 %0, %1, %2, %0;" : "+l"(acc[1][p]) : "l"(av1), "l"(bv[p]));
            }
        }
        __syncthreads();
    }
    float* po = part + (size_t)blockIdx.z * NS2;
#pragma unroll
    for (int m = 0; m < 2; m++) {
        const int row = r0 + ty * 2 + m;
#pragma unroll
        for (int p = 0; p < 4; p++) {
            float lo, hi;
            asm("mov.b64 {%0, %1}, %2;" : "=f"(lo), "=f"(hi) : "l"(acc[m][p]));
            int col = c0 + tx * 8 + 2 * p;
            po[(size_t)row * NS + col]     = lo;
            po[(size_t)row * NS + col + 1] = hi;
        }
    }
}

// batched split-K over T slots: item = z>>2, ksplit = z&3
__global__ void __launch_bounds__(128) k_gskz(
    float* __restrict__ Tb, float* __restrict__ part,
    int a0, int a1, int a2, int a3, int b0s, int b1s, int b2s, int b3s)
{
    const int item = blockIdx.z >> 2;
    const int ks   = blockIdx.z & 3;
    const int asl  = (item == 0) ? a0 : (item == 1) ? a1 : (item == 2) ? a2 : a3;
    const int bsl  = (item == 0) ? b0s : (item == 1) ? b1s : (item == 2) ? b2s : b3s;
    const float* A = Tb + (size_t)asl * NS2;
    const float* B = Tb + (size_t)bsl * NS2;

    __shared__ float As[16][36];
    __shared__ float Bs[16][68];
    const int t  = threadIdx.x;
    const int tx = t & 7, ty = t >> 3;
    const int r0 = blockIdx.y * 32, c0 = blockIdx.x * 64;
    const int kb = ks * 128;

    const int ar = t >> 2, ac4 = (t & 3) * 4;
    const int br = t >> 4, bc4 = (t & 15) * 4;

    unsigned long long acc[2][4];
#pragma unroll
    for (int m = 0; m < 2; m++)
#pragma unroll
        for (int p = 0; p < 4; p++) acc[m][p] = 0ull;

    float4 av = *(const float4*)(A + (size_t)(r0 + ar) * NS + kb + ac4);
    float4 b0 = *(const float4*)(B + (size_t)(kb + br) * NS + c0 + bc4);
    float4 b1 = *(const float4*)(B + (size_t)(kb + br + 8) * NS + c0 + bc4);

    for (int it = 0; it < 8; ++it) {
        As[ac4 + 0][ar] = av.x; As[ac4 + 1][ar] = av.y;
        As[ac4 + 2][ar] = av.z; As[ac4 + 3][ar] = av.w;
        *(float4*)&Bs[br][bc4]     = b0;
        *(float4*)&Bs[br + 8][bc4] = b1;
        __syncthreads();
        if (it < 7) {
            const int k0 = kb + (it + 1) * 16;
            av = *(const float4*)(A + (size_t)(r0 + ar) * NS + k0 + ac4);
            b0 = *(const float4*)(B + (size_t)(k0 + br) * NS + c0 + bc4);
            b1 = *(const float4*)(B + (size_t)(k0 + br + 8) * NS + c0 + bc4);
        }
#pragma unroll
        for (int kk = 0; kk < 16; ++kk) {
            float a0f = As[kk][ty * 2 + 0];
            float a1f = As[kk][ty * 2 + 1];
            ulonglong2 bp0 = *(const ulonglong2*)&Bs[kk][tx * 8];
            ulonglong2 bp1 = *(const ulonglong2*)&Bs[kk][tx * 8 + 4];
            unsigned long long bv[4] = {bp0.x, bp0.y, bp1.x, bp1.y};
            unsigned long long av0, av1;
            asm("mov.b64 %0, {%1, %1};" : "=l"(av0) : "f"(a0f));
            asm("mov.b64 %0, {%1, %1};" : "=l"(av1) : "f"(a1f));
#pragma unroll
            for (int p = 0; p < 4; p++) {
                asm("fma.rn.f32x2 %0, %1, %2, %0;" : "+l"(acc[0][p]) : "l"(av0), "l"(bv[p]));
                asm("fma.rn.f32x2 %0, %1, %2, %0;" : "+l"(acc[1][p]) : "l"(av1), "l"(bv[p]));
            }
        }
        __syncthreads();
    }
    float* po = part + (size_t)(item * 4 + ks) * NS2;
#pragma unroll
    for (int m = 0; m < 2; m++) {
        const int row = r0 + ty * 2 + m;
#pragma unroll
        for (int p = 0; p < 4; p++) {
            float lo, hi;
            asm("mov.b64 {%0, %1}, %2;" : "=f"(lo), "=f"(hi) : "l"(acc[m][p]));
            int col = c0 + tx * 8 + 2 * p;
            po[(size_t)row * NS + col]     = lo;
            po[(size_t)row * NS + col + 1] = hi;
        }
    }
}

// C = (base?) + sum of 4 K-partials (deterministic fixed order)
__global__ void k_gred(float* __restrict__ C, const float* __restrict__ part,
                       const float* __restrict__ base) {
    int idx = blockIdx.x * 256 + threadIdx.x;           // float4 index, NS2/4 total
    size_t o = (size_t)idx * 4;
    float4 p0 = *(const float4*)(part + 0 * (size_t)NS2 + o);
    float4 p1 = *(const float4*)(part + 1 * (size_t)NS2 + o);
    float4 p2 = *(const float4*)(part + 2 * (size_t)NS2 + o);
    float4 p3 = *(const float4*)(part + 3 * (size_t)NS2 + o);
    float4 b = base ? *(const float4*)(base + o) : make_float4(0.f, 0.f, 0.f, 0.f);
    float4 r;
    r.x = b.x + (p0.x + p1.x) + (p2.x + p3.x);
    r.y = b.y + (p0.y + p1.y) + (p2.y + p3.y);
    r.z = b.z + (p0.z + p1.z) + (p2.z + p3.z);
    r.w = b.w + (p0.w + p1.w) + (p2.w + p3.w);
    *(float4*)(C + o) = r;
}

__global__ void k_gredz(float* __restrict__ Tb, const float* __restrict__ part,
                        int d0, int d1, int d2, int d3) {
    const int item = blockIdx.y;
    const int dsl  = (item == 0) ? d0 : (item == 1) ? d1 : (item == 2) ? d2 : d3;
    int idx = blockIdx.x * 256 + threadIdx.x;
    size_t o = (size_t)idx * 4;
    const float* p = part + (size_t)(item * 4) * NS2;
    float4 p0 = *(const float4*)(p + 0 * (size_t)NS2 + o);
    float4 p1 = *(const float4*)(p + 1 * (size_t)NS2 + o);
    float4 p2 = *(const float4*)(p + 2 * (size_t)NS2 + o);
    float4 p3 = *(const float4*)(p + 3 * (size_t)NS2 + o);
    float4 r;
    r.x = (p0.x + p1.x) + (p2.x + p3.x);
    r.y = (p0.y + p1.y) + (p2.y + p3.y);
    r.z = (p0.z + p1.z) + (p2.z + p3.z);
    r.w = (p0.w + p1.w) + (p2.w + p3.w);
    *(float4*)(Tb + (size_t)dsl * NS2 + o) = r;
}

// ---------------- vw[j] = [w1..w4,v] @ T_j (j=1..7, batched) ----------------
__global__ void k_vw(const float* __restrict__ Tb, float* __restrict__ vw) {
    const int j = blockIdx.z + 1;
    const float* T = Tb + (size_t)j * NS2;
    const int c = blockIdx.x * 256 + threadIdx.x;

    __shared__ float v0s[5 * NS];
    for (int i = threadIdx.x; i < 5 * NS; i += 256) v0s[i] = vw[i];
    __syncthreads();

    float acc0 = 0.f, acc1 = 0.f, acc2 = 0.f, acc3 = 0.f, acc4 = 0.f;
    for (int k = 0; k < NS; ++k) {
        float tk = T[(size_t)k * NS + c];
        acc0 += v0s[0 * NS + k] * tk;
        acc1 += v0s[1 * NS + k] * tk;
        acc2 += v0s[2 * NS + k] * tk;
        acc3 += v0s[3 * NS + k] * tk;
        acc4 += v0s[4 * NS + k] * tk;
    }
    float* o = vw + (size_t)j * 5 * NS;
    o[0 * NS + c] = acc0; o[1 * NS + c] = acc1; o[2 * NS + c] = acc2;
    o[3 * NS + c] = acc3; o[4 * NS + c] = acc4;
}

__global__ void k_cv(const float* __restrict__ vw, float* __restrict__ cv) {
    int c = blockIdx.x * 256 + threadIdx.x;
    if (c >= NS) return;
    float acc = 0.f;
    for (int j = 0; j < RAD; ++j) {
        acc += vw[((size_t)j * 5 + 4) * NS + c];
        cv[(size_t)j * NS + c] = acc;
    }
}

// ---------------- grouped E0: one block per group of 8 rows ----------------
__device__ __forceinline__ float dev_interp(const float* __restrict__ Tt,
                                            const float* __restrict__ Tv, float tq) {
    if (tq <= Tt[0])      return Tv[0];
    if (tq >= Tt[ND - 1]) return Tv[ND - 1];
    int lo = 0, hi = ND - 1;
    while (hi - lo > 1) {
        int mid = (lo + hi) >> 1;
        if (Tt[mid] <= tq) lo = mid; else hi = mid;
    }
    float x0 = Tt[lo], x1 = Tt[lo + 1];
    return Tv[lo] + (tq - x0) * (Tv[lo + 1] - Tv[lo]) / (x1 - x0);
}

__global__ void k_buildE0(const float* __restrict__ Tt, const float* __restrict__ Tv,
                          const float* __restrict__ iv, const float* __restrict__ vw,
                          const float* __restrict__ cv, float* __restrict__ E0)
{
    const int g = blockIdx.x;       // 0..NANCH-1, rows 8g..8g+7
    const int t = threadIdx.x;      // 256
    __shared__ float s[15][4];      // d indices 8g-8 .. 8g+6
    const int d0 = 8 * g - 8;
    if (t < 60) {
        int jj = t >> 2, ii = t & 3;
        int d = d0 + jj;
        if (d >= 0) {
            float tq = (float)d * DTC + (float)ii * 10.0f;
            s[jj][ii] = dev_interp(Tt, Tv, tq);
        }
    }
    __syncthreads();

#pragma unroll 1
    for (int q = 0; q < 8; ++q) {
        const int n = 8 * g + q;
        float* row = E0 + (size_t)n * NS;
        if (n == 0) {
            for (int i = t; i < NS; i += 256) row[i] = iv[i];
            continue;
        }
        const int p = ((n - 1) & 7) + 1;
        const float* cvp = cv + (size_t)(p - 1) * NS;
        for (int i = t; i < NS; i += 256) {
            float acc = cvp[i];
            for (int jj = 0; jj < p; ++jj) {
                const float* sj = s[q + 7 - jj];
                const float* base = vw + (size_t)jj * 5 * NS;
                acc += sj[0] * base[i]          + sj[1] * base[NS + i]
                     + sj[2] * base[2 * NS + i] + sj[3] * base[3 * NS + i];
            }
            row[i] = acc;
        }
    }
}

// ---------------- shared GEMV tile body (128 rows x 64 cols, double-buffered) ----------------
__device__ __forceinline__ void mm128x64(
    const float* __restrict__ V, const float* __restrict__ W,
    const long gr[4], const bool vv[4], int kb, int nit, int c0, int t,
    float (*As)[16][132], float (*Bs)[16][68],
    unsigned long long (*acc)[4])
{
    const int tx = t & 7, ty = t >> 3;
    const int ar = t >> 2, ac4 = (t & 3) * 4;
    const int br = t >> 4, bc4 = (t & 15) * 4;
    const float4 f4z = make_float4(0.f, 0.f, 0.f, 0.f);
    float4 av[4], b0v, b1v;
#pragma unroll
    for (int g = 0; g < 4; g++)
        av[g] = vv[g] ? *(const float4*)(V + gr[g] * NS + kb + ac4) : f4z;
    b0v = *(const float4*)(W + (size_t)(kb + br) * NS + c0 + bc4);
    b1v = *(const float4*)(W + (size_t)(kb + br + 8) * NS + c0 + bc4);
#pragma unroll
    for (int g = 0; g < 4; g++) {
        As[0][ac4 + 0][ar + 32 * g] = av[g].x;
        As[0][ac4 + 1][ar + 32 * g] = av[g].y;
        As[0][ac4 + 2][ar + 32 * g] = av[g].z;
        As[0][ac4 + 3][ar + 32 * g] = av[g].w;
    }
    *(float4*)&Bs[0][br][bc4]     = b0v;
    *(float4*)&Bs[0][br + 8][bc4] = b1v;
    __syncthreads();

    for (int it = 0; it < nit; ++it) {
        const int cb = it & 1;
        if (it < nit - 1) {
            const int k0 = kb + (it + 1) * 16;
#pragma unroll
            for (int g = 0; g < 4; g++)
                av[g] = vv[g] ? *(const float4*)(V + gr[g] * NS + k0 + ac4) : f4z;
            b0v = *(const float4*)(W + (size_t)(k0 + br) * NS + c0 + bc4);
            b1v = *(const float4*)(W + (size_t)(k0 + br + 8) * NS + c0 + bc4);
        }
#pragma unroll
        for (int kk = 0; kk < 16; ++kk) {
            float a[8];
            *(float4*)&a[0] = *(const float4*)&As[cb][kk][ty * 8];
            *(float4*)&a[4] = *(const float4*)&As[cb][kk][ty * 8 + 4];
            ulonglong2 bp0 = *(const ulonglong2*)&Bs[cb][kk][tx * 8];
            ulonglong2 bp1 = *(const ulonglong2*)&Bs[cb][kk][tx * 8 + 4];
            unsigned long long bv[4] = {bp0.x, bp0.y, bp1.x, bp1.y};
#pragma unroll
            for (int m = 0; m < 8; m++) {
                unsigned long long avv;
                asm("mov.b64 %0, {%1, %1};" : "=l"(avv) : "f"(a[m]));
#pragma unroll
                for (int p = 0; p < 4; p++)
                    asm("fma.rn.f32x2 %0, %1, %2, %0;"
                        : "+l"(acc[m][p]) : "l"(avv), "l"(bv[p]));
            }
        }
        if (it < nit - 1) {
            const int nb = cb ^ 1;
#pragma unroll
            for (int g = 0; g < 4; g++) {
                As[nb][ac4 + 0][ar + 32 * g] = av[g].x;
                As[nb][ac4 + 1][ar + 32 * g] = av[g].y;
                As[nb][ac4 + 2][ar + 32 * g] = av[g].z;
                As[nb][ac4 + 3][ar + 32 * g] = av[g].w;
            }
            *(float4*)&Bs[nb][br][bc4]     = b0v;
            *(float4*)&Bs[nb][br + 8][bc4] = b1v;
            __syncthreads();
        }
    }
}

// ---------------- split-K anchor BK edge: partials for V[r*S+boff] += V[r*S+aoff]@W ----------------
__global__ void __launch_bounds__(128, 4) k_bk_sk(
    const float* __restrict__ V, const float* __restrict__ W,
    float* __restrict__ part, int S, int aoff, int cnt)
{
    __shared__ float As[2][16][132];
    __shared__ float Bs[2][16][68];
    const int t  = threadIdx.x;
    const int tx = t & 7, ty = t >> 3;
    const int r0 = blockIdx.y * 128;
    const int c0 = blockIdx.x * 64;
    const int ks = blockIdx.z;

    const int ar = t >> 2;
    long gr[4]; bool vv[4];
#pragma unroll
    for (int g = 0; g < 4; g++) {
        int lo = r0 + ar + 32 * g;
        vv[g] = lo < cnt;
        gr[g] = (long)lo * S + aoff;
    }

    unsigned long long acc[8][4];
#pragma unroll
    for (int m = 0; m < 8; m++)
#pragma unroll
        for (int p = 0; p < 4; p++) acc[m][p] = 0ull;

    mm128x64(V, W, gr, vv, ks * 128, 8, c0, t, As, Bs, acc);

#pragma unroll
    for (int m = 0; m < 8; m++) {
        const int r = r0 + ty * 8 + m;
        if (r < cnt) {
            float c[8];
#pragma unroll
            for (int p = 0; p < 4; p++)
                asm("mov.b64 {%0, %1}, %2;"
                    : "=f"(c[2 * p]), "=f"(c[2 * p + 1]) : "l"(acc[m][p]));
            float* prow = part + ((size_t)ks * SKROWS + r) * NS + c0 + tx * 8;
            *(float4*)prow       = make_float4(c[0], c[1], c[2], c[3]);
            *(float4*)(prow + 4) = make_float4(c[4], c[5], c[6], c[7]);
        }
    }
}

__global__ void k_bk_red(float* __restrict__ V, const float* __restrict__ part,
                         int S, int boff, int cnt)
{
    int idx = blockIdx.x * 256 + threadIdx.x;
    int total = cnt * (NS / 4);
    if (idx >= total) return;
    int r  = idx / (NS / 4);
    int c4 = (idx - r * (NS / 4)) * 4;
    float4 p0 = *(const float4*)(part + ((size_t)0 * SKROWS + r) * NS + c4);
    float4 p1 = *(const float4*)(part + ((size_t)1 * SKROWS + r) * NS + c4);
    float4 p2 = *(const float4*)(part + ((size_t)2 * SKROWS + r) * NS + c4);
    float4 p3 = *(const float4*)(part + ((size_t)3 * SKROWS + r) * NS + c4);
    float* dst = V + ((size_t)r * S + boff) * NS + c4;
    float4 d = *(const float4*)dst;
    d.x += (p0.x + p1.x) + (p2.x + p3.x);
    d.y += (p0.y + p1.y) + (p2.y + p3.y);
    d.z += (p0.z + p1.z) + (p2.z + p3.z);
    d.w += (p0.w + p1.w) + (p2.w + p3.w);
    *(float4*)dst = d;
}

// ---------------- flat fill: x[8r+q] = E[8r+q] + (M^q) x[8r], q=1..7 ----------------
__global__ void __launch_bounds__(128, 4) k_fillz(
    float* __restrict__ V, const float* __restrict__ Tb, int cnt)
{
    const int q = blockIdx.z + 1;
    const float* W = Tb + (size_t)q * NS2;

    __shared__ float As[2][16][132];
    __shared__ float Bs[2][16][68];
    const int t  = threadIdx.x;
    const int tx = t & 7, ty = t >> 3;
    const int r0 = blockIdx.y * 128;
    const int c0 = blockIdx.x * 64;

    const int ar = t >> 2;
    long gr[4]; bool vv[4];
#pragma unroll
    for (int g = 0; g < 4; g++) {
        int lo = r0 + ar + 32 * g;
        vv[g] = lo < cnt;
        gr[g] = (long)lo * RAD;
    }

    unsigned long long acc[8][4];
#pragma unroll
    for (int m = 0; m < 8; m++)
#pragma unroll
        for (int p = 0; p < 4; p++) acc[m][p] = 0ull;

    mm128x64(V, W, gr, vv, 0, 32, c0, t, As, Bs, acc);

#pragma unroll
    for (int m = 0; m < 8; m++) {
        const int r = r0 + ty * 8 + m;
        if (r < cnt) {
            const long dr = (long)r * RAD + q;
            float* erow = V + dr * NS + c0 + tx * 8;
            float4 e0 = *(const float4*)erow;
            float4 e1 = *(const float4*)(erow + 4);
            float c[8];
#pragma unroll
            for (int p = 0; p < 4; p++)
                asm("mov.b64 {%0, %1}, %2;"
                    : "=f"(c[2 * p]), "=f"(c[2 * p + 1]) : "l"(acc[m][p]));
            float4 o0 = make_float4(c[0] + e0.x, c[1] + e0.y, c[2] + e0.z, c[3] + e0.w);
            float4 o1 = make_float4(c[4] + e1.x, c[5] + e1.y, c[6] + e1.z, c[7] + e1.w);
            *(float4*)erow       = o0;
            *(float4*)(erow + 4) = o1;
        }
    }
}

// ---------------- host orchestration (graph-capturable, alloc-free) ----------------
extern "C" void kernel_launch(void* const* d_in, const int* in_sizes, int n_in,
                              void* d_out, int out_size) {
    const float* A  = (const float*)d_in[0];
    const float* Bm = (const float*)d_in[1];
    const float* Q  = (const float*)d_in[2];
    const float* Tt = (const float*)d_in[3];
    const float* Tv = (const float*)d_in[4];
    const float* iv = (const float*)d_in[5];
    float* out = (float*)d_out;

    float *Lt, *G1, *G2, *Tb, *vec, *vw, *cv, *part;
    cudaGetSymbolAddress((void**)&Lt,   d_Lt);
    cudaGetSymbolAddress((void**)&G1,   d_G1);
    cudaGetSymbolAddress((void**)&G2,   d_G2);
    cudaGetSymbolAddress((void**)&Tb,   d_T);
    cudaGetSymbolAddress((void**)&vec,  d_vec);
    cudaGetSymbolAddress((void**)&vw,   d_vw);
    cudaGetSymbolAddress((void**)&cv,   d_cv);
    cudaGetSymbolAddress((void**)&part, d_part);

    // Lt = (dt*A)^T
    k_tpose<<<1024, 256>>>(A, Lt);

    // forcing vectors w1..w4, v  (into vw[0])
    k_gh<<<2, 256>>>(Bm, Q, vec + 0 * NS, vec + 1 * NS);
    k_matvec2<<<512, 128>>>(A, vec + 0 * NS, vec + 1 * NS, vec + 2 * NS, vec + 5 * NS, DTC);
    k_matvec2<<<512, 128>>>(A, vec + 2 * NS, vec + 5 * NS, vec + 3 * NS, vec + 6 * NS, DTC);
    k_matvec2<<<512, 128>>>(A, vec + 3 * NS, vec + 6 * NS, vec + 4 * NS, vec + 7 * NS, DTC);
    k_combine<<<2, 256>>>(vec, vw);

    const dim3 gsk(8, 16, 4);
    const int RB = NS2 / 4 / 256;  // 256 blocks for full-matrix reduce

    // G1 = Lt^2 ; T1 = (I + Lt + G1/2) + G1 @ (Lt/6 + G1/24)
    k_gsk<<<gsk, 128>>>(Lt, Lt, part);
    k_gred<<<RB, 256>>>(G1, part, nullptr);
    k_prep1<<<1024, 256>>>(Lt, G1, G2, Tb + 0 * (size_t)NS2);
    k_gsk<<<gsk, 128>>>(G1, G2, part);
    k_gred<<<RB, 256>>>(Tb + 1 * (size_t)NS2, part, Tb + 0 * (size_t)NS2);

    // T2 ; {T3,T4} ; {T5,T6,T7,T8} ; T16 ; T32 ; T64 ; T128
    k_gsk<<<gsk, 128>>>(Tb + 1 * (size_t)NS2, Tb + 1 * (size_t)NS2, part);
    k_gred<<<RB, 256>>>(Tb + 2 * (size_t)NS2, part, nullptr);

    k_gskz<<<dim3(8, 16, 8), 128>>>(Tb, part, 1, 2, 0, 0, 2, 2, 0, 0);
    k_gredz<<<dim3(RB, 2), 256>>>(Tb, part, 3, 4, 0, 0);

    k_gskz<<<dim3(8, 16, 16), 128>>>(Tb, part, 1, 2, 3, 4, 4, 4, 4, 4);
    k_gredz<<<dim3(RB, 4), 256>>>(Tb, part, 5, 6, 7, 8);

    for (int s = 8; s <= 11; ++s) {  // T16(9), T32(10), T64(11), T128(12)
        k_gsk<<<gsk, 128>>>(Tb + (size_t)s * NS2, Tb + (size_t)s * NS2, part);
        k_gred<<<RB, 256>>>(Tb + (size_t)(s + 1) * NS2, part, nullptr);
    }

    // vw[j] = [w,v] @ T_j (j=1..7) ; cv cumsums
    k_vw<<<dim3(2, 1, 7), 256>>>(Tb, vw);
    k_cv<<<2, 256>>>(vw, cv);

    // E0 with within-group-of-8 prefixes (grouped blocks)
    k_buildE0<<<NANCH, 256>>>(Tt, Tv, iv, vw, cv, out);

    // ---- anchor Brent-Kung over 2500 anchors (rows = 8*o), levels j=0..4
    const int Wsel[5] = {8, 9, 10, 11, 12};  // T8, T16, T32, T64, T128
    for (int j = 0; j < 5; ++j) {            // up-sweep
        const int Sa = 1 << (j + 1);
        const int cnt = NANCH >> (j + 1);
        const int Sm = RAD * Sa;
        const int aoff = RAD * ((1 << j) - 1);
        const int boff = RAD * (Sa - 1);
        dim3 gs(8, (cnt + 127) / 128, 4);
        k_bk_sk<<<gs, 128>>>(out, Tb + (size_t)Wsel[j] * NS2, part, Sm, aoff, cnt);
        k_bk_red<<<(cnt * (NS / 4) + 255) / 256, 256>>>(out, part, Sm, boff, cnt);
    }
    for (int j = 4; j >= 0; --j) {           // down-sweep
        const int Sa = 1 << (j + 1);
        const int boffa = Sa - 1 + (1 << j);
        const int cnt = (NANCH - 1 - boffa) / Sa + 1;
        const int Sm = RAD * Sa;
        const int aoff = RAD * (Sa - 1);
        const int boff = RAD * boffa;
        dim3 gs(8, (cnt + 127) / 128, 4);
        k_bk_sk<<<gs, 128>>>(out, Tb + (size_t)Wsel[j] * NS2, part, Sm, aoff, cnt);
        k_bk_red<<<(cnt * (NS / 4) + 255) / 256, 256>>>(out, part, Sm, boff, cnt);
    }

    // ---- flat fill: all non-anchor rows in one launch
    dim3 gf(8, (NANCH + 127) / 128, RAD - 1);
    k_fillz<<<gf, 128>>>(out, Tb, NANCH);
    // result in `out`
}

// round 12
// speedup vs baseline: 1.0622x; 1.0622x over previous
#include <cuda_runtime.h>

#define NS   512
#define NS2  (NS * NS)
#define TN   20000
#define ND   2000
#define DTC  30.0f
#define RAD  8          // fill radix (anchors every 8 rows)
#define NANCH 2500      // TN / RAD
#define SKROWS 1280     // split-K partial rows for anchor BK (max cnt = 1250)

// ---------------- static scratch (no allocations allowed) ----------------
__device__ float d_Lt[NS2];               // (dt*A)^T
__device__ float d_G1[NS2];               // Lt^2
__device__ float d_G2[NS2];               // H = Lt/6 + Lt^2/24
// T slots: 0 = Horner base (I+Lt+Lt^2/2) ; 1..8 = (M^q)^T ; 9=T16,10=T32,11=T64,12=T128
__device__ float d_T[13][NS2];
__device__ float d_vec[8 * NS];           // temps g,h,Lg,L2g,L3g,Lh,L2h,L3h
__device__ float d_vw[RAD * 5 * NS];      // vw[j] = M^j [w1..w4, v]
__device__ float d_cv[RAD * NS];          // cv[p-1] = sum_{j<p} M^j v
__device__ float d_part[16 * NS2];        // split-K partials (16.8 MB, reused)

// ---------------- small helpers ----------------
__global__ void k_tpose(const float* __restrict__ A, float* __restrict__ Lt) {
    int idx = blockIdx.x * blockDim.x + threadIdx.x;
    if (idx < NS2) {
        int i = idx >> 9, j = idx & 511;
        Lt[idx] = DTC * A[j * NS + i];
    }
}

__global__ void k_gh(const float* __restrict__ B, const float* __restrict__ Q,
                     float* __restrict__ g, float* __restrict__ h) {
    int i = blockIdx.x * blockDim.x + threadIdx.x;
    if (i < NS) {
        g[i] = B[i * 9];
        float s = 0.f;
#pragma unroll
        for (int m = 0; m < 8; m++) s += B[i * 9 + 1 + m] * Q[m];
        h[i] = s;
    }
}

__global__ void k_matvec2(const float* __restrict__ A,
                          const float* __restrict__ x1, const float* __restrict__ x2,
                          float* __restrict__ y1, float* __restrict__ y2, float scale) {
    __shared__ float red1[128], red2[128];
    int row = blockIdx.x;
    float s1 = 0.f, s2 = 0.f;
    for (int j = threadIdx.x; j < NS; j += 128) {
        float a = A[row * NS + j];
        s1 += a * x1[j];
        s2 += a * x2[j];
    }
    red1[threadIdx.x] = s1; red2[threadIdx.x] = s2;
    __syncthreads();
    for (int st = 64; st > 0; st >>= 1) {
        if (threadIdx.x < st) {
            red1[threadIdx.x] += red1[threadIdx.x + st];
            red2[threadIdx.x] += red2[threadIdx.x + st];
        }
        __syncthreads();
    }
    if (threadIdx.x == 0) { y1[row] = scale * red1[0]; y2[row] = scale * red2[0]; }
}

// w1..w4, v into vw[0]
__global__ void k_combine(const float* __restrict__ vec, float* __restrict__ vw) {
    int i = blockIdx.x * blockDim.x + threadIdx.x;
    if (i >= NS) return;
    const float G   = vec[0 * NS + i], H   = vec[1 * NS + i];
    const float LG  = vec[2 * NS + i], L2G = vec[3 * NS + i], L3G = vec[4 * NS + i];
    const float LH  = vec[5 * NS + i], L2H = vec[6 * NS + i], L3H = vec[7 * NS + i];
    const float c = DTC / 8.0f;
    vw[0 * NS + i] = c * (G + LG + (L2G + L3G) * (1.0f / 3.0f));
    vw[1 * NS + i] = c * (3.0f * G + 2.0f * LG + L2G);
    vw[2 * NS + i] = c * (3.0f * G + LG);
    vw[3 * NS + i] = c * G;
    vw[4 * NS + i] = DTC * (H + 0.5f * LH + L2H * (1.0f / 6.0f) + L3H * (1.0f / 24.0f));
}

// H = Lt/6 + G1/24 ; base(T0) = I + Lt + G1/2
__global__ void k_prep1(const float* __restrict__ Lt, const float* __restrict__ G1,
                        float* __restrict__ H, float* __restrict__ base) {
    int idx = blockIdx.x * blockDim.x + threadIdx.x;
    if (idx < NS2) {
        int i = idx >> 9, j = idx & 511;
        float l = Lt[idx], g = G1[idx];
        H[idx]    = l * (1.0f / 6.0f) + g * (1.0f / 24.0f);
        base[idx] = l + 0.5f * g + (i == j ? 1.0f : 0.0f);
    }
}

// ---------------- split-K 512^3 GEMM partials (32x64 tile, K chunk 128) ----------------
__global__ void __launch_bounds__(128) k_gsk(
    const float* __restrict__ A, const float* __restrict__ B, float* __restrict__ part)
{
    __shared__ float As[16][36];
    __shared__ float Bs[16][68];
    const int t  = threadIdx.x;
    const int tx = t & 7, ty = t >> 3;
    const int r0 = blockIdx.y * 32, c0 = blockIdx.x * 64;
    const int kb = blockIdx.z * 128;

    const int ar = t >> 2, ac4 = (t & 3) * 4;
    const int br = t >> 4, bc4 = (t & 15) * 4;

    unsigned long long acc[2][4];
#pragma unroll
    for (int m = 0; m < 2; m++)
#pragma unroll
        for (int p = 0; p < 4; p++) acc[m][p] = 0ull;

    float4 av = *(const float4*)(A + (size_t)(r0 + ar) * NS + kb + ac4);
    float4 b0 = *(const float4*)(B + (size_t)(kb + br) * NS + c0 + bc4);
    float4 b1 = *(const float4*)(B + (size_t)(kb + br + 8) * NS + c0 + bc4);

    for (int it = 0; it < 8; ++it) {
        As[ac4 + 0][ar] = av.x; As[ac4 + 1][ar] = av.y;
        As[ac4 + 2][ar] = av.z; As[ac4 + 3][ar] = av.w;
        *(float4*)&Bs[br][bc4]     = b0;
        *(float4*)&Bs[br + 8][bc4] = b1;
        __syncthreads();
        if (it < 7) {
            const int k0 = kb + (it + 1) * 16;
            av = *(const float4*)(A + (size_t)(r0 + ar) * NS + k0 + ac4);
            b0 = *(const float4*)(B + (size_t)(k0 + br) * NS + c0 + bc4);
            b1 = *(const float4*)(B + (size_t)(k0 + br + 8) * NS + c0 + bc4);
        }
#pragma unroll
        for (int kk = 0; kk < 16; ++kk) {
            float a0 = As[kk][ty * 2 + 0];
            float a1 = As[kk][ty * 2 + 1];
            ulonglong2 bp0 = *(const ulonglong2*)&Bs[kk][tx * 8];
            ulonglong2 bp1 = *(const ulonglong2*)&Bs[kk][tx * 8 + 4];
            unsigned long long bv[4] = {bp0.x, bp0.y, bp1.x, bp1.y};
            unsigned long long av0, av1;
            asm("mov.b64 %0, {%1, %1};" : "=l"(av0) : "f"(a0));
            asm("mov.b64 %0, {%1, %1};" : "=l"(av1) : "f"(a1));
#pragma unroll
            for (int p = 0; p < 4; p++) {
                asm("fma.rn.f32x2 %0, %1, %2, %0;" : "+l"(acc[0][p]) : "l"(av0), "l"(bv[p]));
                asm("fma.rn.f32x2 %0, %1, %2, %0;" : "+l"(acc[1][p]) : "l"(av1), "l"(bv[p]));
            }
        }
        __syncthreads();
    }
    float* po = part + (size_t)blockIdx.z * NS2;
#pragma unroll
    for (int m = 0; m < 2; m++) {
        const int row = r0 + ty * 2 + m;
#pragma unroll
        for (int p = 0; p < 4; p++) {
            float lo, hi;
            asm("mov.b64 {%0, %1}, %2;" : "=f"(lo), "=f"(hi) : "l"(acc[m][p]));
            int col = c0 + tx * 8 + 2 * p;
            po[(size_t)row * NS + col]     = lo;
            po[(size_t)row * NS + col + 1] = hi;
        }
    }
}

// batched split-K over T slots: item = z>>2, ksplit = z&3
__global__ void __launch_bounds__(128) k_gskz(
    float* __restrict__ Tb, float* __restrict__ part,
    int a0, int a1, int a2, int a3, int b0s, int b1s, int b2s, int b3s)
{
    const int item = blockIdx.z >> 2;
    const int ks   = blockIdx.z & 3;
    const int asl  = (item == 0) ? a0 : (item == 1) ? a1 : (item == 2) ? a2 : a3;
    const int bsl  = (item == 0) ? b0s : (item == 1) ? b1s : (item == 2) ? b2s : b3s;
    const float* A = Tb + (size_t)asl * NS2;
    const float* B = Tb + (size_t)bsl * NS2;

    __shared__ float As[16][36];
    __shared__ float Bs[16][68];
    const int t  = threadIdx.x;
    const int tx = t & 7, ty = t >> 3;
    const int r0 = blockIdx.y * 32, c0 = blockIdx.x * 64;
    const int kb = ks * 128;

    const int ar = t >> 2, ac4 = (t & 3) * 4;
    const int br = t >> 4, bc4 = (t & 15) * 4;

    unsigned long long acc[2][4];
#pragma unroll
    for (int m = 0; m < 2; m++)
#pragma unroll
        for (int p = 0; p < 4; p++) acc[m][p] = 0ull;

    float4 av = *(const float4*)(A + (size_t)(r0 + ar) * NS + kb + ac4);
    float4 b0 = *(const float4*)(B + (size_t)(kb + br) * NS + c0 + bc4);
    float4 b1 = *(const float4*)(B + (size_t)(kb + br + 8) * NS + c0 + bc4);

    for (int it = 0; it < 8; ++it) {
        As[ac4 + 0][ar] = av.x; As[ac4 + 1][ar] = av.y;
        As[ac4 + 2][ar] = av.z; As[ac4 + 3][ar] = av.w;
        *(float4*)&Bs[br][bc4]     = b0;
        *(float4*)&Bs[br + 8][bc4] = b1;
        __syncthreads();
        if (it < 7) {
            const int k0 = kb + (it + 1) * 16;
            av = *(const float4*)(A + (size_t)(r0 + ar) * NS + k0 + ac4);
            b0 = *(const float4*)(B + (size_t)(k0 + br) * NS + c0 + bc4);
            b1 = *(const float4*)(B + (size_t)(k0 + br + 8) * NS + c0 + bc4);
        }
#pragma unroll
        for (int kk = 0; kk < 16; ++kk) {
            float a0f = As[kk][ty * 2 + 0];
            float a1f = As[kk][ty * 2 + 1];
            ulonglong2 bp0 = *(const ulonglong2*)&Bs[kk][tx * 8];
            ulonglong2 bp1 = *(const ulonglong2*)&Bs[kk][tx * 8 + 4];
            unsigned long long bv[4] = {bp0.x, bp0.y, bp1.x, bp1.y};
            unsigned long long av0, av1;
            asm("mov.b64 %0, {%1, %1};" : "=l"(av0) : "f"(a0f));
            asm("mov.b64 %0, {%1, %1};" : "=l"(av1) : "f"(a1f));
#pragma unroll
            for (int p = 0; p < 4; p++) {
                asm("fma.rn.f32x2 %0, %1, %2, %0;" : "+l"(acc[0][p]) : "l"(av0), "l"(bv[p]));
                asm("fma.rn.f32x2 %0, %1, %2, %0;" : "+l"(acc[1][p]) : "l"(av1), "l"(bv[p]));
            }
        }
        __syncthreads();
    }
    float* po = part + (size_t)(item * 4 + ks) * NS2;
#pragma unroll
    for (int m = 0; m < 2; m++) {
        const int row = r0 + ty * 2 + m;
#pragma unroll
        for (int p = 0; p < 4; p++) {
            float lo, hi;
            asm("mov.b64 {%0, %1}, %2;" : "=f"(lo), "=f"(hi) : "l"(acc[m][p]));
            int col = c0 + tx * 8 + 2 * p;
            po[(size_t)row * NS + col]     = lo;
            po[(size_t)row * NS + col + 1] = hi;
        }
    }
}

// C = (base?) + sum of 4 K-partials (deterministic fixed order)
__global__ void k_gred(float* __restrict__ C, const float* __restrict__ part,
                       const float* __restrict__ base) {
    int idx = blockIdx.x * 256 + threadIdx.x;           // float4 index, NS2/4 total
    size_t o = (size_t)idx * 4;
    float4 p0 = *(const float4*)(part + 0 * (size_t)NS2 + o);
    float4 p1 = *(const float4*)(part + 1 * (size_t)NS2 + o);
    float4 p2 = *(const float4*)(part + 2 * (size_t)NS2 + o);
    float4 p3 = *(const float4*)(part + 3 * (size_t)NS2 + o);
    float4 b = base ? *(const float4*)(base + o) : make_float4(0.f, 0.f, 0.f, 0.f);
    float4 r;
    r.x = b.x + (p0.x + p1.x) + (p2.x + p3.x);
    r.y = b.y + (p0.y + p1.y) + (p2.y + p3.y);
    r.z = b.z + (p0.z + p1.z) + (p2.z + p3.z);
    r.w = b.w + (p0.w + p1.w) + (p2.w + p3.w);
    *(float4*)(C + o) = r;
}

__global__ void k_gredz(float* __restrict__ Tb, const float* __restrict__ part,
                        int d0, int d1, int d2, int d3) {
    const int item = blockIdx.y;
    const int dsl  = (item == 0) ? d0 : (item == 1) ? d1 : (item == 2) ? d2 : d3;
    int idx = blockIdx.x * 256 + threadIdx.x;
    size_t o = (size_t)idx * 4;
    const float* p = part + (size_t)(item * 4) * NS2;
    float4 p0 = *(const float4*)(p + 0 * (size_t)NS2 + o);
    float4 p1 = *(const float4*)(p + 1 * (size_t)NS2 + o);
    float4 p2 = *(const float4*)(p + 2 * (size_t)NS2 + o);
    float4 p3 = *(const float4*)(p + 3 * (size_t)NS2 + o);
    float4 r;
    r.x = (p0.x + p1.x) + (p2.x + p3.x);
    r.y = (p0.y + p1.y) + (p2.y + p3.y);
    r.z = (p0.z + p1.z) + (p2.z + p3.z);
    r.w = (p0.w + p1.w) + (p2.w + p3.w);
    *(float4*)(Tb + (size_t)dsl * NS2 + o) = r;
}

// ---------------- vw[j] = [w1..w4,v] @ T_j (j=1..7, batched) ----------------
__global__ void k_vw(const float* __restrict__ Tb, float* __restrict__ vw) {
    const int j = blockIdx.z + 1;
    const float* T = Tb + (size_t)j * NS2;
    const int c = blockIdx.x * 256 + threadIdx.x;

    __shared__ float v0s[5 * NS];
    for (int i = threadIdx.x; i < 5 * NS; i += 256) v0s[i] = vw[i];
    __syncthreads();

    float acc0 = 0.f, acc1 = 0.f, acc2 = 0.f, acc3 = 0.f, acc4 = 0.f;
    for (int k = 0; k < NS; ++k) {
        float tk = T[(size_t)k * NS + c];
        acc0 += v0s[0 * NS + k] * tk;
        acc1 += v0s[1 * NS + k] * tk;
        acc2 += v0s[2 * NS + k] * tk;
        acc3 += v0s[3 * NS + k] * tk;
        acc4 += v0s[4 * NS + k] * tk;
    }
    float* o = vw + (size_t)j * 5 * NS;
    o[0 * NS + c] = acc0; o[1 * NS + c] = acc1; o[2 * NS + c] = acc2;
    o[3 * NS + c] = acc3; o[4 * NS + c] = acc4;
}

__global__ void k_cv(const float* __restrict__ vw, float* __restrict__ cv) {
    int c = blockIdx.x * 256 + threadIdx.x;
    if (c >= NS) return;
    float acc = 0.f;
    for (int j = 0; j < RAD; ++j) {
        acc += vw[((size_t)j * 5 + 4) * NS + c];
        cv[(size_t)j * NS + c] = acc;
    }
}

// ---------------- grouped E0: one block per group of 8 rows ----------------
__device__ __forceinline__ float dev_interp(const float* __restrict__ Tt,
                                            const float* __restrict__ Tv, float tq) {
    if (tq <= Tt[0])      return Tv[0];
    if (tq >= Tt[ND - 1]) return Tv[ND - 1];
    int lo = 0, hi = ND - 1;
    while (hi - lo > 1) {
        int mid = (lo + hi) >> 1;
        if (Tt[mid] <= tq) lo = mid; else hi = mid;
    }
    float x0 = Tt[lo], x1 = Tt[lo + 1];
    return Tv[lo] + (tq - x0) * (Tv[lo + 1] - Tv[lo]) / (x1 - x0);
}

__global__ void k_buildE0(const float* __restrict__ Tt, const float* __restrict__ Tv,
                          const float* __restrict__ iv, const float* __restrict__ vw,
                          const float* __restrict__ cv, float* __restrict__ E0)
{
    const int g = blockIdx.x;       // rows 8g..8g+7
    const int t = threadIdx.x;      // 256
    __shared__ float s[15][4];      // d indices 8g-8 .. 8g+6
    const int d0 = 8 * g - 8;
    if (t < 60) {
        int jj = t >> 2, ii = t & 3;
        int d = d0 + jj;
        if (d >= 0) {
            float tq = (float)d * DTC + (float)ii * 10.0f;
            s[jj][ii] = dev_interp(Tt, Tv, tq);
        }
    }
    __syncthreads();

#pragma unroll 1
    for (int q = 0; q < 8; ++q) {
        const int n = 8 * g + q;
        float* row = E0 + (size_t)n * NS;
        if (n == 0) {
            for (int i = t; i < NS; i += 256) row[i] = iv[i];
            continue;
        }
        const int p = ((n - 1) & 7) + 1;
        const float* cvp = cv + (size_t)(p - 1) * NS;
        for (int i = t; i < NS; i += 256) {
            float acc = cvp[i];
            for (int jj = 0; jj < p; ++jj) {
                const float* sj = s[q + 7 - jj];
                const float* base = vw + (size_t)jj * 5 * NS;
                acc += sj[0] * base[i]          + sj[1] * base[NS + i]
                     + sj[2] * base[2 * NS + i] + sj[3] * base[3 * NS + i];
            }
            row[i] = acc;
        }
    }
}

// ---------------- split-K anchor BK edge (R10 single-buffer body) ----------------
__global__ void __launch_bounds__(128, 4) k_bk_sk(
    const float* __restrict__ V, const float* __restrict__ W,
    float* __restrict__ part, int S, int aoff, int cnt)
{
    __shared__ float As[16][132];
    __shared__ float Bs[16][68];

    const int t  = threadIdx.x;
    const int tx = t & 7;
    const int ty = t >> 3;
    const int r0 = blockIdx.y * 128;
    const int c0 = blockIdx.x * 64;
    const int z  = blockIdx.z;
    const int kb = z * 128;

    const int  ar  = t >> 2;
    const int  ac4 = (t & 3) * 4;
    long gr[4]; bool v[4];
#pragma unroll
    for (int g = 0; g < 4; g++) {
        int lo = r0 + ar + 32 * g;
        v[g]  = lo < cnt;
        gr[g] = (long)lo * S + aoff;
    }

    const int br  = t >> 4;
    const int bc4 = (t & 15) * 4;

    unsigned long long acc[8][4];
#pragma unroll
    for (int m = 0; m < 8; m++)
#pragma unroll
        for (int p = 0; p < 4; p++) acc[m][p] = 0ull;

    const float4 f4z = make_float4(0.f, 0.f, 0.f, 0.f);
    float4 av[4], b0, b1;
#pragma unroll
    for (int g = 0; g < 4; g++)
        av[g] = v[g] ? *(const float4*)(V + gr[g] * NS + kb + ac4) : f4z;
    b0 = *(const float4*)(W + (size_t)(kb + br) * NS + c0 + bc4);
    b1 = *(const float4*)(W + (size_t)(kb + br + 8) * NS + c0 + bc4);

    for (int it = 0; it < 8; ++it) {
#pragma unroll
        for (int g = 0; g < 4; g++) {
            As[ac4 + 0][ar + 32 * g] = av[g].x;
            As[ac4 + 1][ar + 32 * g] = av[g].y;
            As[ac4 + 2][ar + 32 * g] = av[g].z;
            As[ac4 + 3][ar + 32 * g] = av[g].w;
        }
        *(float4*)&Bs[br][bc4]     = b0;
        *(float4*)&Bs[br + 8][bc4] = b1;
        __syncthreads();

        if (it < 7) {
            const int k0 = kb + (it + 1) * 16;
#pragma unroll
            for (int g = 0; g < 4; g++)
                av[g] = v[g] ? *(const float4*)(V + gr[g] * NS + k0 + ac4) : f4z;
            b0 = *(const float4*)(W + (size_t)(k0 + br) * NS + c0 + bc4);
            b1 = *(const float4*)(W + (size_t)(k0 + br + 8) * NS + c0 + bc4);
        }

#pragma unroll
        for (int kk = 0; kk < 16; ++kk) {
            float a[8];
            *(float4*)&a[0] = *(const float4*)&As[kk][ty * 8];
            *(float4*)&a[4] = *(const float4*)&As[kk][ty * 8 + 4];
            ulonglong2 bp0 = *(const ulonglong2*)&Bs[kk][tx * 8];
            ulonglong2 bp1 = *(const ulonglong2*)&Bs[kk][tx * 8 + 4];
            unsigned long long bv[4] = {bp0.x, bp0.y, bp1.x, bp1.y};
#pragma unroll
            for (int m = 0; m < 8; m++) {
                unsigned long long avv;
                asm("mov.b64 %0, {%1, %1};" : "=l"(avv) : "f"(a[m]));
#pragma unroll
                for (int p = 0; p < 4; p++)
                    asm("fma.rn.f32x2 %0, %1, %2, %0;"
                        : "+l"(acc[m][p]) : "l"(avv), "l"(bv[p]));
            }
        }
        __syncthreads();
    }

#pragma unroll
    for (int m = 0; m < 8; m++) {
        const int r = r0 + ty * 8 + m;
        if (r < cnt) {
            float c[8];
#pragma unroll
            for (int p = 0; p < 4; p++)
                asm("mov.b64 {%0, %1}, %2;"
                    : "=f"(c[2 * p]), "=f"(c[2 * p + 1]) : "l"(acc[m][p]));
            float* prow = part + ((size_t)z * SKROWS + r) * NS + c0 + tx * 8;
            *(float4*)prow       = make_float4(c[0], c[1], c[2], c[3]);
            *(float4*)(prow + 4) = make_float4(c[4], c[5], c[6], c[7]);
        }
    }
}

__global__ void k_bk_red(float* __restrict__ V, const float* __restrict__ part,
                         int S, int boff, int cnt)
{
    int idx = blockIdx.x * 256 + threadIdx.x;
    int total = cnt * (NS / 4);
    if (idx >= total) return;
    int r  = idx / (NS / 4);
    int c4 = (idx - r * (NS / 4)) * 4;
    float4 p0 = *(const float4*)(part + ((size_t)0 * SKROWS + r) * NS + c4);
    float4 p1 = *(const float4*)(part + ((size_t)1 * SKROWS + r) * NS + c4);
    float4 p2 = *(const float4*)(part + ((size_t)2 * SKROWS + r) * NS + c4);
    float4 p3 = *(const float4*)(part + ((size_t)3 * SKROWS + r) * NS + c4);
    float* dst = V + ((size_t)r * S + boff) * NS + c4;
    float4 d = *(const float4*)dst;
    d.x += (p0.x + p1.x) + (p2.x + p3.x);
    d.y += (p0.y + p1.y) + (p2.y + p3.y);
    d.z += (p0.z + p1.z) + (p2.z + p3.z);
    d.w += (p0.w + p1.w) + (p2.w + p3.w);
    *(float4*)dst = d;
}

// ---------------- flat fill (R10 single-buffer body): x[8r+q] = E[8r+q] + (M^q) x[8r] ----------------
__global__ void __launch_bounds__(128, 4) k_fillz(
    float* __restrict__ V, const float* __restrict__ Tb, int cnt)
{
    const int q = blockIdx.z + 1;
    const float* W = Tb + (size_t)q * NS2;

    __shared__ float As[16][132];
    __shared__ float Bs[16][68];

    const int t  = threadIdx.x;
    const int tx = t & 7;
    const int ty = t >> 3;
    const int r0 = blockIdx.y * 128;
    const int c0 = blockIdx.x * 64;

    const int  ar  = t >> 2;
    const int  ac4 = (t & 3) * 4;
    long gr[4]; bool v[4];
#pragma unroll
    for (int g = 0; g < 4; g++) {
        int lo = r0 + ar + 32 * g;
        v[g]  = lo < cnt;
        gr[g] = (long)lo * RAD;
    }

    const int br  = t >> 4;
    const int bc4 = (t & 15) * 4;

    unsigned long long acc[8][4];
#pragma unroll
    for (int m = 0; m < 8; m++)
#pragma unroll
        for (int p = 0; p < 4; p++) acc[m][p] = 0ull;

    const float4 f4z = make_float4(0.f, 0.f, 0.f, 0.f);
    float4 av[4], b0, b1;
#pragma unroll
    for (int g = 0; g < 4; g++)
        av[g] = v[g] ? *(const float4*)(V + gr[g] * NS + ac4) : f4z;
    b0 = *(const float4*)(W + (size_t)br * NS + c0 + bc4);
    b1 = *(const float4*)(W + (size_t)(br + 8) * NS + c0 + bc4);

    for (int it = 0; it < 32; ++it) {
#pragma unroll
        for (int g = 0; g < 4; g++) {
            As[ac4 + 0][ar + 32 * g] = av[g].x;
            As[ac4 + 1][ar + 32 * g] = av[g].y;
            As[ac4 + 2][ar + 32 * g] = av[g].z;
            As[ac4 + 3][ar + 32 * g] = av[g].w;
        }
        *(float4*)&Bs[br][bc4]     = b0;
        *(float4*)&Bs[br + 8][bc4] = b1;
        __syncthreads();

        if (it < 31) {
            const int k0 = (it + 1) * 16;
#pragma unroll
            for (int g = 0; g < 4; g++)
                av[g] = v[g] ? *(const float4*)(V + gr[g] * NS + k0 + ac4) : f4z;
            b0 = *(const float4*)(W + (size_t)(k0 + br) * NS + c0 + bc4);
            b1 = *(const float4*)(W + (size_t)(k0 + br + 8) * NS + c0 + bc4);
        }

#pragma unroll
        for (int kk = 0; kk < 16; ++kk) {
            float a[8];
            *(float4*)&a[0] = *(const float4*)&As[kk][ty * 8];
            *(float4*)&a[4] = *(const float4*)&As[kk][ty * 8 + 4];
            ulonglong2 bp0 = *(const ulonglong2*)&Bs[kk][tx * 8];
            ulonglong2 bp1 = *(const ulonglong2*)&Bs[kk][tx * 8 + 4];
            unsigned long long bv[4] = {bp0.x, bp0.y, bp1.x, bp1.y};
#pragma unroll
            for (int m = 0; m < 8; m++) {
                unsigned long long avv;
                asm("mov.b64 %0, {%1, %1};" : "=l"(avv) : "f"(a[m]));
#pragma unroll
                for (int p = 0; p < 4; p++)
                    asm("fma.rn.f32x2 %0, %1, %2, %0;"
                        : "+l"(acc[m][p]) : "l"(avv), "l"(bv[p]));
            }
        }
        __syncthreads();
    }

#pragma unroll
    for (int m = 0; m < 8; m++) {
        const int r = r0 + ty * 8 + m;
        if (r < cnt) {
            const long dr = (long)r * RAD + q;
            float* erow = V + dr * NS + c0 + tx * 8;
            float4 e0 = *(const float4*)erow;
            float4 e1 = *(const float4*)(erow + 4);
            float c[8];
#pragma unroll
            for (int p = 0; p < 4; p++)
                asm("mov.b64 {%0, %1}, %2;"
                    : "=f"(c[2 * p]), "=f"(c[2 * p + 1]) : "l"(acc[m][p]));
            float4 o0 = make_float4(c[0] + e0.x, c[1] + e0.y, c[2] + e0.z, c[3] + e0.w);
            float4 o1 = make_float4(c[4] + e1.x, c[5] + e1.y, c[6] + e1.z, c[7] + e1.w);
            *(float4*)erow       = o0;
            *(float4*)(erow + 4) = o1;
        }
    }
}

// ---------------- host orchestration (graph-capturable, alloc-free) ----------------
extern "C" void kernel_launch(void* const* d_in, const int* in_sizes, int n_in,
                              void* d_out, int out_size) {
    const float* A  = (const float*)d_in[0];
    const float* Bm = (const float*)d_in[1];
    const float* Q  = (const float*)d_in[2];
    const float* Tt = (const float*)d_in[3];
    const float* Tv = (const float*)d_in[4];
    const float* iv = (const float*)d_in[5];
    float* out = (float*)d_out;

    float *Lt, *G1, *G2, *Tb, *vec, *vw, *cv, *part;
    cudaGetSymbolAddress((void**)&Lt,   d_Lt);
    cudaGetSymbolAddress((void**)&G1,   d_G1);
    cudaGetSymbolAddress((void**)&G2,   d_G2);
    cudaGetSymbolAddress((void**)&Tb,   d_T);
    cudaGetSymbolAddress((void**)&vec,  d_vec);
    cudaGetSymbolAddress((void**)&vw,   d_vw);
    cudaGetSymbolAddress((void**)&cv,   d_cv);
    cudaGetSymbolAddress((void**)&part, d_part);

    // Lt = (dt*A)^T
    k_tpose<<<1024, 256>>>(A, Lt);

    // forcing vectors w1..w4, v  (into vw[0])
    k_gh<<<2, 256>>>(Bm, Q, vec + 0 * NS, vec + 1 * NS);
    k_matvec2<<<512, 128>>>(A, vec + 0 * NS, vec + 1 * NS, vec + 2 * NS, vec + 5 * NS, DTC);
    k_matvec2<<<512, 128>>>(A, vec + 2 * NS, vec + 5 * NS, vec + 3 * NS, vec + 6 * NS, DTC);
    k_matvec2<<<512, 128>>>(A, vec + 3 * NS, vec + 6 * NS, vec + 4 * NS, vec + 7 * NS, DTC);
    k_combine<<<2, 256>>>(vec, vw);

    const dim3 gsk(8, 16, 4);
    const int RB = NS2 / 4 / 256;  // 256 blocks for full-matrix reduce

    // G1 = Lt^2 ; T1 = (I + Lt + G1/2) + G1 @ (Lt/6 + G1/24)
    k_gsk<<<gsk, 128>>>(Lt, Lt, part);
    k_gred<<<RB, 256>>>(G1, part, nullptr);
    k_prep1<<<1024, 256>>>(Lt, G1, G2, Tb + 0 * (size_t)NS2);
    k_gsk<<<gsk, 128>>>(G1, G2, part);
    k_gred<<<RB, 256>>>(Tb + 1 * (size_t)NS2, part, Tb + 0 * (size_t)NS2);

    // T2 ; {T3,T4} ; {T5,T6,T7,T8} ; T16 ; T32 ; T64 ; T128
    k_gsk<<<gsk, 128>>>(Tb + 1 * (size_t)NS2, Tb + 1 * (size_t)NS2, part);
    k_gred<<<RB, 256>>>(Tb + 2 * (size_t)NS2, part, nullptr);

    k_gskz<<<dim3(8, 16, 8), 128>>>(Tb, part, 1, 2, 0, 0, 2, 2, 0, 0);
    k_gredz<<<dim3(RB, 2), 256>>>(Tb, part, 3, 4, 0, 0);

    k_gskz<<<dim3(8, 16, 16), 128>>>(Tb, part, 1, 2, 3, 4, 4, 4, 4, 4);
    k_gredz<<<dim3(RB, 4), 256>>>(Tb, part, 5, 6, 7, 8);

    for (int s = 8; s <= 11; ++s) {  // T16(9), T32(10), T64(11), T128(12)
        k_gsk<<<gsk, 128>>>(Tb + (size_t)s * NS2, Tb + (size_t)s * NS2, part);
        k_gred<<<RB, 256>>>(Tb + (size_t)(s + 1) * NS2, part, nullptr);
    }

    // vw[j] = [w,v] @ T_j (j=1..7) ; cv cumsums
    k_vw<<<dim3(2, 1, 7), 256>>>(Tb, vw);
    k_cv<<<2, 256>>>(vw, cv);

    // E0 with within-group-of-8 prefixes (grouped blocks)
    k_buildE0<<<NANCH, 256>>>(Tt, Tv, iv, vw, cv, out);

    // ---- anchor Brent-Kung over 2500 anchors (rows = 8*o), levels j=0..4
    const int Wsel[5] = {8, 9, 10, 11, 12};  // T8, T16, T32, T64, T128
    for (int j = 0; j < 5; ++j) {            // up-sweep
        const int Sa = 1 << (j + 1);
        const int cnt = NANCH >> (j + 1);
        const int Sm = RAD * Sa;
        const int aoff = RAD * ((1 << j) - 1);
        const int boff = RAD * (Sa - 1);
        dim3 gs(8, (cnt + 127) / 128, 4);
        k_bk_sk<<<gs, 128>>>(out, Tb + (size_t)Wsel[j] * NS2, part, Sm, aoff, cnt);
        k_bk_red<<<(cnt * (NS / 4) + 255) / 256, 256>>>(out, part, Sm, boff, cnt);
    }
    for (int j = 4; j >= 0; --j) {           // down-sweep
        const int Sa = 1 << (j + 1);
        const int boffa = Sa - 1 + (1 << j);
        const int cnt = (NANCH - 1 - boffa) / Sa + 1;
        const int Sm = RAD * Sa;
        const int aoff = RAD * (Sa - 1);
        const int boff = RAD * boffa;
        dim3 gs(8, (cnt + 127) / 128, 4);
        k_bk_sk<<<gs, 128>>>(out, Tb + (size_t)Wsel[j] * NS2, part, Sm, aoff, cnt);
        k_bk_red<<<(cnt * (NS / 4) + 255) / 256, 256>>>(out, part, Sm, boff, cnt);
    }

    // ---- flat fill: all non-anchor rows in one launch
    dim3 gf(8, (NANCH + 127) / 128, RAD - 1);
    k_fillz<<<gf, 128>>>(out, Tb, NANCH);
    // result in `out`
}